// round 7
// baseline (speedup 1.0000x reference)
#include <cuda_runtime.h>

// ---------------- problem constants ----------------
#define NPTS   524288
#define TILE   128
#define HALF   64
#define NTILES (NPTS / TILE)     // 4096
#define TPB    256
#define NCTA   148
#define PADP   132

#define DH   64
#define EMB  32
#define DIRD 27
#define FEAT 15
#define LAT  128
#define RGBK (EMB + DIRD + FEAT) // 74

// ---------------- smem layout (float offsets) ----------------
#define S_OCCW0 0
#define S_OCCW1 (S_OCCW0 + 32*64)
#define S_OCCW2 (S_OCCW1 + 64*64)
#define S_RGBW0 (S_OCCW2 + 64*16)
#define S_RGBW1 (S_RGBW0 + 74*64)
#define S_RGBW2 (S_RGBW1 + 64*64)
#define S_OCCB0 (S_RGBW2 + 64*3)
#define S_OCCB1 (S_OCCB0 + 64)
#define S_OCCB2 (S_OCCB1 + 64)
#define S_RGBB1 (S_OCCB2 + 16)
#define S_RGBB2 (S_RGBB1 + 64)
#define S_LATB  (S_RGBB2 + 4)
#define S_OCCV  (S_LATB + 64)
#define S_XB    (S_OCCV + 128)      // [74][PADP]
#define S_HB    (S_XB + 74*PADP)    // [64][PADP]
#define S_GB    (S_HB + 64*PADP)    // [64][PADP]
#define S_TOTAL (S_GB + 64*PADP)    // 43260 floats = 173040 bytes

typedef unsigned long long u64t;

#define FMA_F32X2(d, a, b, c) \
    asm("fma.rn.f32x2 %0, %1, %2, %3;" : "=l"(d) : "l"(a), "l"(b), "l"(c))
#define PACK_SPLAT(out, x) \
    asm("mov.b64 %0, {%1, %1};" : "=l"(out) : "r"(__float_as_uint(x)))
#define UNPACK_F32X2U(lo, hi, in) \
    asm("mov.b64 {%0, %1}, %2;" : "=r"(lo), "=r"(hi) : "l"(in))

// named barrier per 128-thread half (ids 1 and 2)
static __device__ __forceinline__ void barh(int half) {
    asm volatile("bar.sync %0, 128;" :: "r"(half + 1) : "memory");
}

__device__ __forceinline__ float sp_fast(float x) {
    float e = __expf(x);
    float y = __logf(1.0f + e);
    return (x > 20.0f) ? x : y;
}
__device__ __forceinline__ float sigmoid_fast(float x) {
    return 1.0f / (1.0f + __expf(-x));
}

// Dense layer for one 64-point half: Y[64 x 64] = act(X @ W + b)
// X transposed in smem X[k][p] (stride PADP), half occupies columns hb..hb+63.
// Thread tile: 4 points x 8 neurons, neuron-pair f32x2 accumulators.
template<int K, bool ACT>
__device__ __forceinline__ void layer64h(float* sm, int xoff, int woff,
                                         int boff, int yoff, int t128, int hb)
{
    const int ty = t128 >> 3;   // 0..15 : points hb + 4*ty ..
    const int tx = t128 & 7;    // neurons 8*tx .. 8*tx+7
    const float* xp = sm + xoff + hb + 4 * ty;
    const float* wp = sm + woff + 8 * tx;

    u64t acc[4][4];
    {
        const u64t* bp = (const u64t*)(sm + boff + 8 * tx);
        u64t b0 = bp[0], b1 = bp[1], b2 = bp[2], b3 = bp[3];
        #pragma unroll
        for (int p = 0; p < 4; p++) {
            acc[p][0] = b0; acc[p][1] = b1; acc[p][2] = b2; acc[p][3] = b3;
        }
    }

    #pragma unroll 8
    for (int k = 0; k < K; k++) {
        float4 xv = *(const float4*)(xp + k * PADP);
        u64t xs0, xs1, xs2, xs3;
        PACK_SPLAT(xs0, xv.x); PACK_SPLAT(xs1, xv.y);
        PACK_SPLAT(xs2, xv.z); PACK_SPLAT(xs3, xv.w);
        ulonglong2 wA = *(const ulonglong2*)(wp + k * 64);
        ulonglong2 wB = *(const ulonglong2*)(wp + k * 64 + 4);
        FMA_F32X2(acc[0][0], xs0, wA.x, acc[0][0]);
        FMA_F32X2(acc[0][1], xs0, wA.y, acc[0][1]);
        FMA_F32X2(acc[0][2], xs0, wB.x, acc[0][2]);
        FMA_F32X2(acc[0][3], xs0, wB.y, acc[0][3]);
        FMA_F32X2(acc[1][0], xs1, wA.x, acc[1][0]);
        FMA_F32X2(acc[1][1], xs1, wA.y, acc[1][1]);
        FMA_F32X2(acc[1][2], xs1, wB.x, acc[1][2]);
        FMA_F32X2(acc[1][3], xs1, wB.y, acc[1][3]);
        FMA_F32X2(acc[2][0], xs2, wA.x, acc[2][0]);
        FMA_F32X2(acc[2][1], xs2, wA.y, acc[2][1]);
        FMA_F32X2(acc[2][2], xs2, wB.x, acc[2][2]);
        FMA_F32X2(acc[2][3], xs2, wB.y, acc[2][3]);
        FMA_F32X2(acc[3][0], xs3, wA.x, acc[3][0]);
        FMA_F32X2(acc[3][1], xs3, wA.y, acc[3][1]);
        FMA_F32X2(acc[3][2], xs3, wB.x, acc[3][2]);
        FMA_F32X2(acc[3][3], xs3, wB.y, acc[3][3]);
    }

    float vals[4][8];
    #pragma unroll
    for (int p = 0; p < 4; p++) {
        #pragma unroll
        for (int np = 0; np < 4; np++) {
            unsigned int ulo, uhi;
            UNPACK_F32X2U(ulo, uhi, acc[p][np]);
            float lo = __uint_as_float(ulo);
            float hi = __uint_as_float(uhi);
            if (ACT) { lo = sp_fast(lo); hi = sp_fast(hi); }
            vals[p][2*np]   = lo;
            vals[p][2*np+1] = hi;
        }
    }
    float* yp = sm + yoff + hb + 4 * ty;
    #pragma unroll
    for (int n = 0; n < 8; n++) {
        *(float4*)(yp + (8 * tx + n) * PADP) =
            make_float4(vals[0][n], vals[1][n], vals[2][n], vals[3][n]);
    }
}

__global__ __launch_bounds__(TPB, 1)
void nerf_mlp_gemm_kernel(
    const float* __restrict__ embedded,
    const float* __restrict__ embedded_dir,
    const float* __restrict__ occ_W0, const float* __restrict__ occ_b0,
    const float* __restrict__ occ_W1, const float* __restrict__ occ_b1,
    const float* __restrict__ occ_W2, const float* __restrict__ occ_b2,
    const float* __restrict__ rgb_W0, const float* __restrict__ rgb_b0,
    const float* __restrict__ rgb_W1, const float* __restrict__ rgb_b1,
    const float* __restrict__ rgb_W2, const float* __restrict__ rgb_b2,
    const float* __restrict__ rgb_latent,
    const int*   __restrict__ latent_index,
    float* __restrict__ out)
{
    extern __shared__ float sm[];
    const int tid  = threadIdx.x;
    const int half = tid >> 7;          // 0 or 1 (warps 0-3 / 4-7)
    const int t128 = tid & 127;
    const int hb   = half * HALF;       // point-column base in smem buffers

    // ---------- stage weights once ----------
    for (int t = tid; t < 32*64;  t += TPB) sm[S_OCCW0 + t] = occ_W0[t];
    for (int t = tid; t < 64*64;  t += TPB) sm[S_OCCW1 + t] = occ_W1[t];
    for (int t = tid; t < 64*16;  t += TPB) sm[S_OCCW2 + t] = occ_W2[t];
    for (int t = tid; t < 74*64;  t += TPB) sm[S_RGBW0 + t] = rgb_W0[t];
    for (int t = tid; t < 64*64;  t += TPB) sm[S_RGBW1 + t] = rgb_W1[t];
    for (int t = tid; t < 64*3;   t += TPB) sm[S_RGBW2 + t] = rgb_W2[t];
    for (int t = tid; t < 64; t += TPB) {
        sm[S_OCCB0 + t] = occ_b0[t];
        sm[S_OCCB1 + t] = occ_b1[t];
        sm[S_RGBB1 + t] = rgb_b1[t];
    }
    if (tid < 16) sm[S_OCCB2 + tid] = occ_b2[tid];
    if (tid >= 16 && tid < 19) sm[S_RGBB2 + tid - 16] = rgb_b2[tid - 16];

    // fold constant latent into rgb layer-0 bias (reads globals only)
    if (tid >= 192) {
        const int j = tid - 192;
        const int li = *latent_index;
        const float* lrow = rgb_latent + li * LAT;
        float acc = rgb_b0[j];
        #pragma unroll 8
        for (int l = 0; l < LAT; l++)
            acc = fmaf(lrow[l], rgb_W0[(RGBK + l) * 64 + j], acc);
        sm[S_LATB + j] = acc;
    }
    __syncthreads();

    // ---------- persistent tile loop; halves run decoupled ----------
    for (int tile = blockIdx.x; tile < NTILES; tile += NCTA) {
        const int g0 = tile * TILE;
        const int gh = g0 + hb;          // first global point of this half

        // stage this half's inputs (transposed)
        {
            const float* src = embedded + (size_t)gh * EMB;
            for (int idx = t128; idx < HALF * EMB; idx += 128) {
                int p = idx >> 5, k = idx & 31;
                sm[S_XB + k * PADP + hb + p] = src[idx];
            }
            const float* sd = embedded_dir + (size_t)gh * DIRD;
            for (int idx = t128; idx < HALF * DIRD; idx += 128) {
                int p = idx / DIRD, k = idx - p * DIRD;
                sm[S_XB + (EMB + k) * PADP + hb + p] = sd[idx];
            }
        }
        barh(half);

        // occ layer 0: 32 -> 64, softplus
        layer64h<EMB, true>(sm, S_XB, S_OCCW0, S_OCCB0, S_HB, t128, hb);
        barh(half);
        // occ layer 1: 64 -> 64, softplus
        layer64h<DH, true>(sm, S_HB, S_OCCW1, S_OCCB1, S_GB, t128, hb);
        barh(half);

        // occ layer 2: 64 -> 16 (linear). 2 threads/point, 8 outputs each.
        {
            const int p  = hb + (t128 >> 1);
            const int n0 = (t128 & 1) * 8;
            float acc[8];
            {
                const float4* b4 = (const float4*)(sm + S_OCCB2 + n0);
                float4 b0 = b4[0], b1 = b4[1];
                acc[0]=b0.x; acc[1]=b0.y; acc[2]=b0.z; acc[3]=b0.w;
                acc[4]=b1.x; acc[5]=b1.y; acc[6]=b1.z; acc[7]=b1.w;
            }
            const float* xp = sm + S_GB + p;
            const float* wp = sm + S_OCCW2 + n0;
            #pragma unroll 8
            for (int k = 0; k < DH; k++) {
                float x = xp[k * PADP];
                float4 w0 = *(const float4*)(wp + k * 16);
                float4 w1 = *(const float4*)(wp + k * 16 + 4);
                acc[0] = fmaf(x, w0.x, acc[0]);
                acc[1] = fmaf(x, w0.y, acc[1]);
                acc[2] = fmaf(x, w0.z, acc[2]);
                acc[3] = fmaf(x, w0.w, acc[3]);
                acc[4] = fmaf(x, w1.x, acc[4]);
                acc[5] = fmaf(x, w1.y, acc[5]);
                acc[6] = fmaf(x, w1.z, acc[6]);
                acc[7] = fmaf(x, w1.w, acc[7]);
            }
            #pragma unroll
            for (int j = 0; j < 8; j++) {
                int n = n0 + j;
                if (n == 0) {
                    float o = 1.0f - __expf(-sp_fast(acc[0]));
                    sm[S_OCCV + p] = o;
                    out[(size_t)NPTS * 4 + g0 + p] = o;
                } else {
                    sm[S_XB + (EMB + DIRD + n - 1) * PADP + p] = acc[j];
                }
            }
        }
        barh(half);

        // rgb layer 0: 74 -> 64, softplus (bias = latent-folded)
        layer64h<RGBK, true>(sm, S_XB, S_RGBW0, S_LATB, S_HB, t128, hb);
        barh(half);
        // rgb layer 1: 64 -> 64, softplus
        layer64h<DH, true>(sm, S_HB, S_RGBW1, S_RGBB1, S_GB, t128, hb);
        barh(half);

        // rgb layer 2: 64 -> 3, sigmoid
        if (t128 < HALF) {
            const int p = hb + t128;
            float a0 = sm[S_RGBB2 + 0];
            float a1 = sm[S_RGBB2 + 1];
            float a2 = sm[S_RGBB2 + 2];
            const float* xp = sm + S_GB + p;
            const float* wp = sm + S_RGBW2;
            #pragma unroll 8
            for (int k = 0; k < DH; k++) {
                float x = xp[k * PADP];
                a0 = fmaf(x, wp[k * 3 + 0], a0);
                a1 = fmaf(x, wp[k * 3 + 1], a1);
                a2 = fmaf(x, wp[k * 3 + 2], a2);
            }
            float4 raw = make_float4(sigmoid_fast(a0), sigmoid_fast(a1),
                                     sigmoid_fast(a2), sm[S_OCCV + p]);
            reinterpret_cast<float4*>(out)[g0 + p] = raw;
        }
        barh(half);   // protect buffers before next staging
    }
}

extern "C" void kernel_launch(void* const* d_in, const int* in_sizes, int n_in,
                              void* d_out, int out_size) {
    const float* embedded     = (const float*)d_in[0];
    const float* embedded_dir = (const float*)d_in[1];
    const float* occ_W0 = (const float*)d_in[2];
    const float* occ_b0 = (const float*)d_in[3];
    const float* occ_W1 = (const float*)d_in[4];
    const float* occ_b1 = (const float*)d_in[5];
    const float* occ_W2 = (const float*)d_in[6];
    const float* occ_b2 = (const float*)d_in[7];
    const float* rgb_W0 = (const float*)d_in[8];
    const float* rgb_b0 = (const float*)d_in[9];
    const float* rgb_W1 = (const float*)d_in[10];
    const float* rgb_b1 = (const float*)d_in[11];
    const float* rgb_W2 = (const float*)d_in[12];
    const float* rgb_b2 = (const float*)d_in[13];
    const float* rgb_latent = (const float*)d_in[14];
    const int*   latent_index = (const int*)d_in[15];

    const size_t smem_bytes = (size_t)S_TOTAL * sizeof(float);
    cudaFuncSetAttribute(nerf_mlp_gemm_kernel,
                         cudaFuncAttributeMaxDynamicSharedMemorySize,
                         (int)smem_bytes);

    nerf_mlp_gemm_kernel<<<NCTA, TPB, smem_bytes>>>(
        embedded, embedded_dir,
        occ_W0, occ_b0, occ_W1, occ_b1, occ_W2, occ_b2,
        rgb_W0, rgb_b0, rgb_W1, rgb_b1, rgb_W2, rgb_b2,
        rgb_latent, latent_index,
        (float*)d_out);
}